// round 13
// baseline (speedup 1.0000x reference)
#include <cuda_runtime.h>
#include <cuda_bf16.h>
#include <cstdint>

// Embedding gather: out[row, :] = w[x[row], :]
// x: [16384] int32, w: [50257, 1024] fp32, out: [16384, 1024] fp32
//
// Measured steady-state ceiling: DRAM write-drain of the 64 MB output
// (~3.8 TB/s = HBM3e write BW). Reads are already L2-resident.
// This round: shave DRAM write traffic with a FRACTIONAL store policy —
// 25% of store lines evict_last (stay in L2, overwritten in place each graph
// replay => never drain), 75% evict_first (stream to DRAM). Uniform
// distribution avoids R10's contiguous-range set-hotspotting failure.
// Pinned budget: ~57 MB hot w + 16 MB out = 73 MB << 126 MB L2.

#define EMB_DIM 1024
#define VEC_PER_ROW (EMB_DIM / 4)   // 256 float4 per row
#define ROWS_PER_BLOCK 4

__device__ __forceinline__ float4 ldg_el(const float4* p, uint64_t pol) {
    float4 v;
    asm volatile("ld.global.nc.L2::cache_hint.v4.f32 {%0,%1,%2,%3}, [%4], %5;"
                 : "=f"(v.x), "=f"(v.y), "=f"(v.z), "=f"(v.w)
                 : "l"(p), "l"(pol));
    return v;
}

__device__ __forceinline__ void stg_pol(float4* p, float4 v, uint64_t pol) {
    asm volatile("st.global.L2::cache_hint.v4.f32 [%0], {%1,%2,%3,%4}, %5;"
                 :: "l"(p), "f"(v.x), "f"(v.y), "f"(v.z), "f"(v.w), "l"(pol)
                 : "memory");
}

__global__ void __launch_bounds__(256, 8) embedding_gather_kernel(
    const int* __restrict__ x,
    const float4* __restrict__ w,
    float4* __restrict__ out,
    int n_rows)
{
    uint64_t pol_r, pol_w;
    // Reads: full evict_last (hot gathered rows stay resident)
    asm("createpolicy.fractional.L2::evict_last.b64 %0, 1.0;" : "=l"(pol_r));
    // Writes: 25% evict_last (L2-resident, rewritten in place each replay),
    //         75% evict_first (streamed out, minimal L2 disturbance)
    asm("createpolicy.fractional.L2::evict_last.L2::evict_first.b64 %0, 0.25;"
        : "=l"(pol_w));

    int row0 = blockIdx.x * ROWS_PER_BLOCK;
    int c = threadIdx.x;                       // column slot 0..255

    // Uniform index load: 4 ints as one int4 (16B-aligned since row0%4==0)
    int4 ia = __ldg((const int4*)(x + row0));

    const float4* base = w + c;

    // Front-batched independent gathers: MLP = 4, L2-pinned
    float4 v0 = ldg_el(base + (size_t)ia.x * VEC_PER_ROW, pol_r);
    float4 v1 = ldg_el(base + (size_t)ia.y * VEC_PER_ROW, pol_r);
    float4 v2 = ldg_el(base + (size_t)ia.z * VEC_PER_ROW, pol_r);
    float4 v3 = ldg_el(base + (size_t)ia.w * VEC_PER_ROW, pol_r);

    float4* dst = out + (size_t)row0 * VEC_PER_ROW + c;
    stg_pol(dst + 0 * VEC_PER_ROW, v0, pol_w);
    stg_pol(dst + 1 * VEC_PER_ROW, v1, pol_w);
    stg_pol(dst + 2 * VEC_PER_ROW, v2, pol_w);
    stg_pol(dst + 3 * VEC_PER_ROW, v3, pol_w);
}

extern "C" void kernel_launch(void* const* d_in, const int* in_sizes, int n_in,
                              void* d_out, int out_size) {
    const int*    x = (const int*)d_in[0];          // [16384] indices
    const float4* w = (const float4*)d_in[1];       // [50257*1024] fp32 as float4
    float4*       o = (float4*)d_out;

    int n_rows = in_sizes[0];                       // 16384
    int n_blocks = n_rows / ROWS_PER_BLOCK;         // 4096
    embedding_gather_kernel<<<n_blocks, 256>>>(x, w, o, n_rows);
}